// round 2
// baseline (speedup 1.0000x reference)
#include <cuda_runtime.h>
#include <math.h>
#include <stdint.h>

#define NN 50000
#define EE 800000
#define DD 128
#define BB 32
#define LL 3

// ---------------- scratch (static device globals; no allocation) ----------------
__device__ float g_h[NN * DD];        // node state
__device__ float g_hpre[NN * DD];     // pre-layernorm
__device__ float g_Z[NN * 384];       // [P | Q | T] per node
__device__ float g_Hacc[NN * DD];     // scatter accumulator
__device__ float g_tp[BB * DD];       // time projection
__device__ float g_dist[EE];
__device__ float g_deg[NN];
__device__ float g_invdeg[NN];
__device__ float g_Wk1[LL * DD * 384];  // packed [W1a | W1b | nw1]
__device__ float g_bk1[LL * 384];
__device__ float g_Wk3[LL * 256 * DD];  // packed [nw2 ; ew2]
__device__ float g_bk3[LL * DD];        // nb2 + eb2
__device__ int   g_is64;

__device__ __forceinline__ float silu_f(float x) { return x / (1.f + __expf(-x)); }

__device__ __forceinline__ float to_tf32(float x) {
    float r;
    asm("cvt.rna.tf32.f32 %0, %1;" : "=f"(r) : "f"(x));
    return r;
}

__device__ __forceinline__ long long idx_at(const void* p, long long i) {
    if (g_is64) return ((const long long*)p)[i];
    return (long long)((const int*)p)[i];
}

// ---------------- dtype detection for edge_index / batch -------------------------
__global__ void detect_idx_kernel(const unsigned* w) {
    int is64 = 1;
    for (int i = 1; i < 256; i += 2)
        if (w[i] != 0u) { is64 = 0; break; }
    g_is64 = is64;
}

// ---------------- weight packing -------------------------------------------------
__global__ void pack_w_kernel(const float* __restrict__ ew1, const float* __restrict__ eb1,
                              const float* __restrict__ ew2, const float* __restrict__ eb2,
                              const float* __restrict__ nw1, const float* __restrict__ nb1,
                              const float* __restrict__ nw2, const float* __restrict__ nb2) {
    int idx = blockIdx.x * blockDim.x + threadIdx.x;
    if (idx < LL * DD * 384) {
        int l = idx / (DD * 384);
        int rem = idx % (DD * 384);
        int k = rem / 384;
        int j = rem % 384;
        float v;
        if (j < 128)       v = ew1[l * 257 * 128 + k * 128 + j];
        else if (j < 256)  v = ew1[l * 257 * 128 + (128 + k) * 128 + (j - 128)];
        else               v = nw1[l * 128 * 128 + k * 128 + (j - 256)];
        g_Wk1[idx] = v;
    }
    if (idx < LL * 256 * DD) {
        int l = idx / (256 * DD);
        int rem = idx % (256 * DD);
        int k = rem / DD;
        int j = rem % DD;
        float v = (k < 128) ? nw2[l * 128 * 128 + k * 128 + j]
                            : ew2[l * 128 * 128 + (k - 128) * 128 + j];
        g_Wk3[idx] = v;
    }
    if (idx < LL * 384) {
        int l = idx / 384;
        int j = idx % 384;
        float v;
        if (j < 128)      v = eb1[l * 128 + j];
        else if (j < 256) v = 0.f;
        else              v = nb1[l * 128 + (j - 256)];
        g_bk1[idx] = v;
    }
    if (idx < LL * DD) {
        g_bk3[idx] = nb2[idx] + eb2[idx];
    }
}

// ---------------- time MLP --------------------------------------------------------
__global__ void time_mlp_kernel(const float* __restrict__ te,
                                const float* __restrict__ tw1, const float* __restrict__ tb1,
                                const float* __restrict__ tw2, const float* __restrict__ tb2) {
    __shared__ float row[DD];
    __shared__ float hid[DD];
    int b = blockIdx.x;
    int j = threadIdx.x;
    row[j] = te[b * DD + j];
    __syncthreads();
    float s = tb1[j];
    #pragma unroll 8
    for (int k = 0; k < DD; k++) s = fmaf(row[k], tw1[k * DD + j], s);
    hid[j] = silu_f(s);
    __syncthreads();
    float s2 = tb2[j];
    #pragma unroll 8
    for (int k = 0; k < DD; k++) s2 = fmaf(hid[k], tw2[k * DD + j], s2);
    g_tp[b * DD + j] = s2;
}

// ---------------- h = x + tp[batch] ----------------------------------------------
__global__ void init_h_kernel(const float* __restrict__ x, const void* __restrict__ batch) {
    int idx = blockIdx.x * blockDim.x + threadIdx.x;
    if (idx >= NN * DD) return;
    int n = idx >> 7;
    int d = idx & 127;
    long long bi = idx_at(batch, n);
    g_h[idx] = x[idx] + g_tp[(int)bi * DD + d];
}

// ---------------- zero kernels ----------------------------------------------------
__global__ void zero_deg_kernel() {
    int i = blockIdx.x * blockDim.x + threadIdx.x;
    if (i < NN) g_deg[i] = 0.f;
}
__global__ void zero_hacc_kernel() {
    int i = blockIdx.x * blockDim.x + threadIdx.x;
    if (i < NN * DD) g_Hacc[i] = 0.f;
}

// ---------------- edge prep: dist + degree ----------------------------------------
__global__ void prep_edges_kernel(const void* __restrict__ ei, const float* __restrict__ pos) {
    int e = blockIdx.x * blockDim.x + threadIdx.x;
    if (e >= EE) return;
    int r = (int)idx_at(ei, e);
    int c = (int)idx_at(ei, (long long)EE + e);
    float dx = pos[r * 3 + 0] - pos[c * 3 + 0];
    float dy = pos[r * 3 + 1] - pos[c * 3 + 1];
    float dz = pos[r * 3 + 2] - pos[c * 3 + 2];
    g_dist[e] = sqrtf(dx * dx + dy * dy + dz * dz);
    atomicAdd(&g_deg[c], 1.f);
}

__global__ void invdeg_kernel() {
    int i = blockIdx.x * blockDim.x + threadIdx.x;
    if (i < NN) g_invdeg[i] = 1.f / fmaxf(g_deg[i], 1.f);
}

// ---------------- edge message: silu(P[col]+Q[row]+dist*w1c); scatter-add ---------
__global__ void edge_msg_kernel(const void* __restrict__ ei, const float* __restrict__ w1c) {
    int t = blockIdx.x * blockDim.x + threadIdx.x;
    int e = t >> 5;
    int lane = t & 31;
    if (e >= EE) return;
    int r = (int)idx_at(ei, e);
    int c = (int)idx_at(ei, (long long)EE + e);
    float dist = g_dist[e];
    const float4 p = *(const float4*)(g_Z + (long long)c * 384 + lane * 4);
    const float4 q = *(const float4*)(g_Z + (long long)r * 384 + 128 + lane * 4);
    const float4 wc = *(const float4*)(w1c + lane * 4);
    float4 v;
    v.x = silu_f(p.x + q.x + dist * wc.x);
    v.y = silu_f(p.y + q.y + dist * wc.y);
    v.z = silu_f(p.z + q.z + dist * wc.z);
    v.w = silu_f(p.w + q.w + dist * wc.w);
    float* dst = g_Hacc + (long long)c * DD + lane * 4;
    asm volatile("red.global.add.v4.f32 [%0], {%1,%2,%3,%4};"
                 :: "l"(dst), "f"(v.x), "f"(v.y), "f"(v.z), "f"(v.w) : "memory");
}

// ---------------- tf32 tensor-core GEMM (3xTF32 precision) -------------------------
// C[nrows,ncols] = [A0 | A1*invdeg] @ W + bias (+silu on cols>=silu_from) (+resid)
// BM=128, BN=64, BK=16, 256 threads = 8 warps (4 row x 2 col), warp tile 32x32.
#define MMA_TF32(c, a, b0, b1)                                                    \
    asm volatile("mma.sync.aligned.m16n8k8.row.col.f32.tf32.tf32.f32 "            \
                 "{%0,%1,%2,%3}, {%4,%5,%6,%7}, {%8,%9}, {%0,%1,%2,%3};"          \
                 : "+f"(c[0]), "+f"(c[1]), "+f"(c[2]), "+f"(c[3])                 \
                 : "r"(a[0]), "r"(a[1]), "r"(a[2]), "r"(a[3]), "r"(b0), "r"(b1))

template<bool DUAL, bool RESID>
__global__ __launch_bounds__(256)
void gemm_tc(const float* __restrict__ A0, int lda0,
             const float* __restrict__ A1, int lda1,
             const float* __restrict__ W,  const float* __restrict__ bias,
             const float* __restrict__ resid, float* __restrict__ C, int ldc,
             int nrows, int ncols, int Ktot, int silu_from) {
    __shared__ float As_hi[128][20];   // [m][k], ld=20 -> conflict-free frag reads
    __shared__ float As_lo[128][20];
    __shared__ float Bs_hi[16][72];    // [k][n], ld=72 -> conflict-free frag reads
    __shared__ float Bs_lo[16][72];

    const int tid  = threadIdx.x;
    const int lane = tid & 31;
    const int warp = tid >> 5;
    const int wm = (warp >> 1) * 32;   // warp row offset inside block tile
    const int wn = (warp & 1) * 32;    // warp col offset inside block tile
    const int row0 = blockIdx.y * 128;
    const int col0 = blockIdx.x * 64;

    float acc[2][4][4];
    #pragma unroll
    for (int mi = 0; mi < 2; mi++)
        #pragma unroll
        for (int ni = 0; ni < 4; ni++)
            #pragma unroll
            for (int j = 0; j < 4; j++) acc[mi][ni][j] = 0.f;

    for (int kt = 0; kt < Ktot; kt += 16) {
        // ---- load A tile: 128 rows x 16 k = 512 float4, 2 per thread ----
        #pragma unroll
        for (int it = 0; it < 2; it++) {
            int idx = tid + it * 256;
            int m = idx >> 2;
            int k4 = (idx & 3) * 4;
            int grow = row0 + m;
            float4 v = make_float4(0.f, 0.f, 0.f, 0.f);
            if (grow < nrows) {
                int gk = kt + k4;
                if (!DUAL || gk < 128) {
                    v = *(const float4*)(A0 + (size_t)grow * lda0 + gk);
                } else {
                    v = *(const float4*)(A1 + (size_t)grow * lda1 + (gk - 128));
                    float s = g_invdeg[grow];
                    v.x *= s; v.y *= s; v.z *= s; v.w *= s;
                }
            }
            float hx = to_tf32(v.x), hy = to_tf32(v.y), hz = to_tf32(v.z), hw = to_tf32(v.w);
            As_hi[m][k4 + 0] = hx; As_lo[m][k4 + 0] = to_tf32(v.x - hx);
            As_hi[m][k4 + 1] = hy; As_lo[m][k4 + 1] = to_tf32(v.y - hy);
            As_hi[m][k4 + 2] = hz; As_lo[m][k4 + 2] = to_tf32(v.z - hz);
            As_hi[m][k4 + 3] = hw; As_lo[m][k4 + 3] = to_tf32(v.w - hw);
        }
        // ---- load B tile: 16 k x 64 n = 256 float4, 1 per thread ----
        {
            int k = tid >> 4;
            int n4 = (tid & 15) * 4;
            float4 v = *(const float4*)(W + (size_t)(kt + k) * ncols + col0 + n4);
            float hx = to_tf32(v.x), hy = to_tf32(v.y), hz = to_tf32(v.z), hw = to_tf32(v.w);
            Bs_hi[k][n4 + 0] = hx; Bs_lo[k][n4 + 0] = to_tf32(v.x - hx);
            Bs_hi[k][n4 + 1] = hy; Bs_lo[k][n4 + 1] = to_tf32(v.y - hy);
            Bs_hi[k][n4 + 2] = hz; Bs_lo[k][n4 + 2] = to_tf32(v.z - hz);
            Bs_hi[k][n4 + 3] = hw; Bs_lo[k][n4 + 3] = to_tf32(v.w - hw);
        }
        __syncthreads();

        #pragma unroll
        for (int k8 = 0; k8 < 16; k8 += 8) {
            const int kk = k8 + (lane & 3);
            uint32_t ah[2][4], al[2][4];
            #pragma unroll
            for (int mi = 0; mi < 2; mi++) {
                int r = wm + mi * 16 + (lane >> 2);
                ah[mi][0] = __float_as_uint(As_hi[r][kk]);
                ah[mi][1] = __float_as_uint(As_hi[r + 8][kk]);
                ah[mi][2] = __float_as_uint(As_hi[r][kk + 4]);
                ah[mi][3] = __float_as_uint(As_hi[r + 8][kk + 4]);
                al[mi][0] = __float_as_uint(As_lo[r][kk]);
                al[mi][1] = __float_as_uint(As_lo[r + 8][kk]);
                al[mi][2] = __float_as_uint(As_lo[r][kk + 4]);
                al[mi][3] = __float_as_uint(As_lo[r + 8][kk + 4]);
            }
            #pragma unroll
            for (int ni = 0; ni < 4; ni++) {
                int c = wn + ni * 8 + (lane >> 2);
                uint32_t bh0 = __float_as_uint(Bs_hi[kk][c]);
                uint32_t bh1 = __float_as_uint(Bs_hi[kk + 4][c]);
                uint32_t bl0 = __float_as_uint(Bs_lo[kk][c]);
                uint32_t bl1 = __float_as_uint(Bs_lo[kk + 4][c]);
                #pragma unroll
                for (int mi = 0; mi < 2; mi++) {
                    MMA_TF32(acc[mi][ni], ah[mi], bh0, bh1);
                    MMA_TF32(acc[mi][ni], al[mi], bh0, bh1);
                    MMA_TF32(acc[mi][ni], ah[mi], bl0, bl1);
                }
            }
        }
        __syncthreads();
    }

    // ---- epilogue ----
    #pragma unroll
    for (int mi = 0; mi < 2; mi++) {
        #pragma unroll
        for (int ni = 0; ni < 4; ni++) {
            int rbase = row0 + wm + mi * 16 + (lane >> 2);
            int cbase = col0 + wn + ni * 8 + (lane & 3) * 2;
            #pragma unroll
            for (int rr = 0; rr < 2; rr++) {
                int grow = rbase + rr * 8;
                if (grow >= nrows) continue;
                #pragma unroll
                for (int cc = 0; cc < 2; cc++) {
                    int gc = cbase + cc;
                    float v = acc[mi][ni][rr * 2 + cc] + bias[gc];
                    if (gc >= silu_from) v = silu_f(v);
                    if (RESID) v += resid[(size_t)grow * ldc + gc];
                    C[(size_t)grow * ldc + gc] = v;
                }
            }
        }
    }
}

// ---------------- layernorm: h = LN(hpre) ------------------------------------------
__global__ void ln_kernel(const float* __restrict__ gamma, const float* __restrict__ beta) {
    int gt = blockIdx.x * blockDim.x + threadIdx.x;
    int n = gt >> 5;
    int lane = gt & 31;
    if (n >= NN) return;
    float4 v = *(const float4*)(g_hpre + (long long)n * DD + lane * 4);
    float s = v.x + v.y + v.z + v.w;
    #pragma unroll
    for (int o = 16; o; o >>= 1) s += __shfl_xor_sync(0xffffffffu, s, o);
    float mean = s * (1.f / 128.f);
    float dx = v.x - mean, dy = v.y - mean, dz = v.z - mean, dw = v.w - mean;
    float sq = dx * dx + dy * dy + dz * dz + dw * dw;
    #pragma unroll
    for (int o = 16; o; o >>= 1) sq += __shfl_xor_sync(0xffffffffu, sq, o);
    float rs = rsqrtf(sq * (1.f / 128.f) + 1e-5f);
    float4 g4 = *(const float4*)(gamma + lane * 4);
    float4 b4 = *(const float4*)(beta + lane * 4);
    float4 o4;
    o4.x = dx * rs * g4.x + b4.x;
    o4.y = dy * rs * g4.y + b4.y;
    o4.z = dz * rs * g4.z + b4.z;
    o4.w = dw * rs * g4.w + b4.w;
    *(float4*)(g_h + (long long)n * DD + lane * 4) = o4;
}

// ---------------- final output: [h (N*D) | pos (N*3)] ------------------------------
__global__ void copy_out_kernel(const float* __restrict__ pos, float* __restrict__ out) {
    int i = blockIdx.x * blockDim.x + threadIdx.x;
    if (i < NN * DD) out[i] = g_h[i];
    if (i < NN * 3) out[NN * DD + i] = pos[i];
}

// ==================================================================================
extern "C" void kernel_launch(void* const* d_in, const int* in_sizes, int n_in,
                              void* d_out, int out_size) {
    const float* x        = (const float*)d_in[0];
    const float* pos      = (const float*)d_in[1];
    const float* time_emb = (const float*)d_in[2];
    const float* tw1      = (const float*)d_in[3];
    const float* tb1      = (const float*)d_in[4];
    const float* tw2      = (const float*)d_in[5];
    const float* tb2      = (const float*)d_in[6];
    const float* nw1      = (const float*)d_in[7];
    const float* nb1      = (const float*)d_in[8];
    const float* nw2      = (const float*)d_in[9];
    const float* nb2      = (const float*)d_in[10];
    const float* ew1      = (const float*)d_in[11];
    const float* eb1      = (const float*)d_in[12];
    const float* ew2      = (const float*)d_in[13];
    const float* eb2      = (const float*)d_in[14];
    const float* lng      = (const float*)d_in[15];
    const float* lnb      = (const float*)d_in[16];
    const void*  ei       = d_in[17];
    const void*  batch    = d_in[18];
    float* out = (float*)d_out;

    float *pH, *pHpre, *pZ, *pHacc, *pWk1, *pbk1, *pWk3, *pbk3;
    cudaGetSymbolAddress((void**)&pH,    g_h);
    cudaGetSymbolAddress((void**)&pHpre, g_hpre);
    cudaGetSymbolAddress((void**)&pZ,    g_Z);
    cudaGetSymbolAddress((void**)&pHacc, g_Hacc);
    cudaGetSymbolAddress((void**)&pWk1,  g_Wk1);
    cudaGetSymbolAddress((void**)&pbk1,  g_bk1);
    cudaGetSymbolAddress((void**)&pWk3,  g_Wk3);
    cudaGetSymbolAddress((void**)&pbk3,  g_bk3);

    detect_idx_kernel<<<1, 1>>>((const unsigned*)ei);
    pack_w_kernel<<<(LL * DD * 384 + 255) / 256, 256>>>(ew1, eb1, ew2, eb2, nw1, nb1, nw2, nb2);
    time_mlp_kernel<<<BB, DD>>>(time_emb, tw1, tb1, tw2, tb2);
    init_h_kernel<<<(NN * DD + 255) / 256, 256>>>(x, batch);
    zero_deg_kernel<<<(NN + 255) / 256, 256>>>();
    prep_edges_kernel<<<(EE + 255) / 256, 256>>>(ei, pos);
    invdeg_kernel<<<(NN + 255) / 256, 256>>>();

    const int rowTiles = (NN + 127) / 128;  // 391
    for (int l = 0; l < LL; l++) {
        // Z = [P | Q | silu(T)] = h @ [W1a | W1b | nw1] + [b1 | 0 | nb1]
        gemm_tc<false, false><<<dim3(6, rowTiles), 256>>>(
            pH, DD, nullptr, 0,
            pWk1 + (long long)l * DD * 384, pbk1 + l * 384,
            nullptr, pZ, 384, NN, 384, 128, 256);

        zero_hacc_kernel<<<(NN * DD + 255) / 256, 256>>>();
        edge_msg_kernel<<<(EE * 32 + 255) / 256, 256>>>(ei, ew1 + (long long)l * 257 * 128 + 256 * 128);

        // hpre = h + [silu(T) | Hacc*invdeg] @ [nw2 ; ew2] + (nb2 + eb2)
        gemm_tc<true, true><<<dim3(2, rowTiles), 256>>>(
            pZ + 256, 384, pHacc, DD,
            pWk3 + (long long)l * 256 * DD, pbk3 + l * DD,
            pH, pHpre, DD, NN, DD, 256, 1 << 30);

        ln_kernel<<<(NN * 32 + 255) / 256, 256>>>(lng + l * DD, lnb + l * DD);
    }

    copy_out_kernel<<<(NN * DD + 255) / 256, 256>>>(pos, out);
}

// round 3
// speedup vs baseline: 1.1565x; 1.1565x over previous
#include <cuda_runtime.h>
#include <math.h>
#include <stdint.h>

#define NN 50000
#define EE 800000
#define DD 128
#define BB 32
#define LL 3
#define NB ((NN + 255) / 256)

// ---------------- scratch (static device globals; no allocation) ----------------
__device__ float g_h[NN * DD];        // node state
__device__ float g_Z[NN * 384];       // [P | Q | T] per node
__device__ float g_Hacc[NN * DD];     // aggregated messages (pre-scaled by invdeg)
__device__ float g_tp[BB * DD];       // time projection
__device__ float g_dist[EE];          // per-edge distance (original edge order)
__device__ float g_invdeg[NN];
__device__ int   g_cnt[NN];           // in-degree
__device__ int   g_off[NN];           // CSR offsets
__device__ int   g_cursor[NN];        // scatter cursors
__device__ int   g_bsum[NB + 1];      // scan partials
__device__ int   g_er[EE];            // CSR: source node per slot
__device__ float g_edist[EE];         // CSR: distance per slot
__device__ float g_Wk1[LL * DD * 384];  // packed [W1a | W1b | nw1]
__device__ float g_bk1[LL * 384];
__device__ float g_Wk3[LL * 256 * DD];  // packed [nw2 ; ew2]
__device__ float g_bk3[LL * DD];        // nb2 + eb2
__device__ int   g_is64;

__device__ __forceinline__ float silu_f(float x) { return x / (1.f + __expf(-x)); }

__device__ __forceinline__ float to_tf32(float x) {
    float r;
    asm("cvt.rna.tf32.f32 %0, %1;" : "=f"(r) : "f"(x));
    return r;
}

__device__ __forceinline__ long long idx_at(const void* p, long long i) {
    if (g_is64) return ((const long long*)p)[i];
    return (long long)((const int*)p)[i];
}

// ---------------- dtype detection for edge_index / batch -------------------------
__global__ void detect_idx_kernel(const unsigned* w) {
    int is64 = 1;
    for (int i = 1; i < 256; i += 2)
        if (w[i] != 0u) { is64 = 0; break; }
    g_is64 = is64;
}

// ---------------- weight packing -------------------------------------------------
__global__ void pack_w_kernel(const float* __restrict__ ew1, const float* __restrict__ eb1,
                              const float* __restrict__ ew2, const float* __restrict__ eb2,
                              const float* __restrict__ nw1, const float* __restrict__ nb1,
                              const float* __restrict__ nw2, const float* __restrict__ nb2) {
    int idx = blockIdx.x * blockDim.x + threadIdx.x;
    if (idx < LL * DD * 384) {
        int l = idx / (DD * 384);
        int rem = idx % (DD * 384);
        int k = rem / 384;
        int j = rem % 384;
        float v;
        if (j < 128)       v = ew1[l * 257 * 128 + k * 128 + j];
        else if (j < 256)  v = ew1[l * 257 * 128 + (128 + k) * 128 + (j - 128)];
        else               v = nw1[l * 128 * 128 + k * 128 + (j - 256)];
        g_Wk1[idx] = v;
    }
    if (idx < LL * 256 * DD) {
        int l = idx / (256 * DD);
        int rem = idx % (256 * DD);
        int k = rem / DD;
        int j = rem % DD;
        float v = (k < 128) ? nw2[l * 128 * 128 + k * 128 + j]
                            : ew2[l * 128 * 128 + (k - 128) * 128 + j];
        g_Wk3[idx] = v;
    }
    if (idx < LL * 384) {
        int l = idx / 384;
        int j = idx % 384;
        float v;
        if (j < 128)      v = eb1[l * 128 + j];
        else if (j < 256) v = 0.f;
        else              v = nb1[l * 128 + (j - 256)];
        g_bk1[idx] = v;
    }
    if (idx < LL * DD) {
        g_bk3[idx] = nb2[idx] + eb2[idx];
    }
}

// ---------------- time MLP --------------------------------------------------------
__global__ void time_mlp_kernel(const float* __restrict__ te,
                                const float* __restrict__ tw1, const float* __restrict__ tb1,
                                const float* __restrict__ tw2, const float* __restrict__ tb2) {
    __shared__ float row[DD];
    __shared__ float hid[DD];
    int b = blockIdx.x;
    int j = threadIdx.x;
    row[j] = te[b * DD + j];
    __syncthreads();
    float s = tb1[j];
    #pragma unroll 8
    for (int k = 0; k < DD; k++) s = fmaf(row[k], tw1[k * DD + j], s);
    hid[j] = silu_f(s);
    __syncthreads();
    float s2 = tb2[j];
    #pragma unroll 8
    for (int k = 0; k < DD; k++) s2 = fmaf(hid[k], tw2[k * DD + j], s2);
    g_tp[b * DD + j] = s2;
}

// ---------------- h = x + tp[batch]; also zero g_cnt -------------------------------
__global__ void init_h_kernel(const float* __restrict__ x, const void* __restrict__ batch) {
    int idx = blockIdx.x * blockDim.x + threadIdx.x;
    if (idx < NN) g_cnt[idx] = 0;
    if (idx >= NN * DD) return;
    int n = idx >> 7;
    int d = idx & 127;
    long long bi = idx_at(batch, n);
    g_h[idx] = x[idx] + g_tp[(int)bi * DD + d];
}

// ---------------- edge prep: dist + int degree histogram ---------------------------
__global__ void prep_edges_kernel(const void* __restrict__ ei, const float* __restrict__ pos) {
    int e = blockIdx.x * blockDim.x + threadIdx.x;
    if (e >= EE) return;
    int r = (int)idx_at(ei, e);
    int c = (int)idx_at(ei, (long long)EE + e);
    float dx = pos[r * 3 + 0] - pos[c * 3 + 0];
    float dy = pos[r * 3 + 1] - pos[c * 3 + 1];
    float dz = pos[r * 3 + 2] - pos[c * 3 + 2];
    g_dist[e] = sqrtf(dx * dx + dy * dy + dz * dz);
    atomicAdd(&g_cnt[c], 1);
}

// ---------------- CSR scan: block-local exclusive scan + partials ------------------
__global__ void scanA_kernel() {
    __shared__ int sm[256];
    int i = blockIdx.x * 256 + threadIdx.x;
    int v = (i < NN) ? g_cnt[i] : 0;
    sm[threadIdx.x] = v;
    __syncthreads();
    #pragma unroll
    for (int o = 1; o < 256; o <<= 1) {
        int u = 0;
        if ((int)threadIdx.x >= o) u = sm[threadIdx.x - o];
        __syncthreads();
        sm[threadIdx.x] += u;
        __syncthreads();
    }
    if (i < NN) g_off[i] = sm[threadIdx.x] - v;   // exclusive within block
    if (threadIdx.x == 255) g_bsum[blockIdx.x] = sm[255];
}

__global__ void scanB_kernel() {
    // single thread exclusive scan of NB partials (NB=196, trivial)
    if (threadIdx.x == 0) {
        int run = 0;
        for (int j = 0; j < NB; j++) {
            int t = g_bsum[j];
            g_bsum[j] = run;
            run += t;
        }
    }
}

__global__ void scanC_kernel() {
    int i = blockIdx.x * blockDim.x + threadIdx.x;
    if (i >= NN) return;
    int o = g_off[i] + g_bsum[i >> 8];
    g_off[i] = o;
    g_cursor[i] = o;
    g_invdeg[i] = 1.f / (float)max(g_cnt[i], 1);
}

// ---------------- scatter edges into CSR order -------------------------------------
__global__ void scatter_kernel(const void* __restrict__ ei) {
    int e = blockIdx.x * blockDim.x + threadIdx.x;
    if (e >= EE) return;
    int r = (int)idx_at(ei, e);
    int c = (int)idx_at(ei, (long long)EE + e);
    int p = atomicAdd(&g_cursor[c], 1);
    g_er[p] = r;
    g_edist[p] = g_dist[e];
}

// ---------------- aggregation: warp per node, no atomics ---------------------------
// Hacc[n] = invdeg[n] * sum_e silu(P[n] + Q[src(e)] + dist(e)*w1c)
__global__ void agg_kernel(const float* __restrict__ w1c) {
    int t = blockIdx.x * blockDim.x + threadIdx.x;
    int n = t >> 5;
    int lane = t & 31;
    if (n >= NN) return;
    int start = g_off[n];
    int cnt = g_cnt[n];
    const float4 wc = *(const float4*)(w1c + lane * 4);
    const float4 p  = *(const float4*)(g_Z + (size_t)n * 384 + lane * 4);
    float4 acc = make_float4(0.f, 0.f, 0.f, 0.f);
    for (int i = 0; i < cnt; i++) {
        int r = g_er[start + i];
        float d = g_edist[start + i];
        const float4 q = *(const float4*)(g_Z + (size_t)r * 384 + 128 + lane * 4);
        acc.x += silu_f(p.x + q.x + d * wc.x);
        acc.y += silu_f(p.y + q.y + d * wc.y);
        acc.z += silu_f(p.z + q.z + d * wc.z);
        acc.w += silu_f(p.w + q.w + d * wc.w);
    }
    float s = g_invdeg[n];
    acc.x *= s; acc.y *= s; acc.z *= s; acc.w *= s;
    *(float4*)(g_Hacc + (size_t)n * DD + lane * 4) = acc;
}

// ---------------- 3xTF32 mma helper -------------------------------------------------
#define MMA_TF32(c, a, b0, b1)                                                    \
    asm volatile("mma.sync.aligned.m16n8k8.row.col.f32.tf32.tf32.f32 "            \
                 "{%0,%1,%2,%3}, {%4,%5,%6,%7}, {%8,%9}, {%0,%1,%2,%3};"          \
                 : "+f"(c[0]), "+f"(c[1]), "+f"(c[2]), "+f"(c[3])                 \
                 : "r"(a[0]), "r"(a[1]), "r"(a[2]), "r"(a[3]), "r"(b0), "r"(b1))

// ---------------- GEMM1: Z = h @ Wk1 + bk1, silu on cols >= 256 --------------------
// BM=128, BN=64, BK=16, 256 threads, warp grid 4x2, warp tile 32x32.
__global__ __launch_bounds__(256)
void gemm1_kernel(const float* __restrict__ A,
                  const float* __restrict__ W, const float* __restrict__ bias,
                  float* __restrict__ C) {
    __shared__ float As_hi[128][20];
    __shared__ float As_lo[128][20];
    __shared__ float Bs_hi[16][72];
    __shared__ float Bs_lo[16][72];

    const int tid  = threadIdx.x;
    const int lane = tid & 31;
    const int warp = tid >> 5;
    const int wm = (warp >> 1) * 32;
    const int wn = (warp & 1) * 32;
    const int row0 = blockIdx.y * 128;
    const int col0 = blockIdx.x * 64;
    const int ncols = 384;

    float acc[2][4][4];
    #pragma unroll
    for (int mi = 0; mi < 2; mi++)
        #pragma unroll
        for (int ni = 0; ni < 4; ni++)
            #pragma unroll
            for (int j = 0; j < 4; j++) acc[mi][ni][j] = 0.f;

    for (int kt = 0; kt < 128; kt += 16) {
        #pragma unroll
        for (int it = 0; it < 2; it++) {
            int idx = tid + it * 256;
            int m = idx >> 2;
            int k4 = (idx & 3) * 4;
            int grow = row0 + m;
            float4 v = make_float4(0.f, 0.f, 0.f, 0.f);
            if (grow < NN) v = *(const float4*)(A + (size_t)grow * DD + kt + k4);
            float hx = to_tf32(v.x), hy = to_tf32(v.y), hz = to_tf32(v.z), hw = to_tf32(v.w);
            As_hi[m][k4 + 0] = hx; As_lo[m][k4 + 0] = to_tf32(v.x - hx);
            As_hi[m][k4 + 1] = hy; As_lo[m][k4 + 1] = to_tf32(v.y - hy);
            As_hi[m][k4 + 2] = hz; As_lo[m][k4 + 2] = to_tf32(v.z - hz);
            As_hi[m][k4 + 3] = hw; As_lo[m][k4 + 3] = to_tf32(v.w - hw);
        }
        {
            int k = tid >> 4;
            int n4 = (tid & 15) * 4;
            float4 v = *(const float4*)(W + (size_t)(kt + k) * ncols + col0 + n4);
            float hx = to_tf32(v.x), hy = to_tf32(v.y), hz = to_tf32(v.z), hw = to_tf32(v.w);
            Bs_hi[k][n4 + 0] = hx; Bs_lo[k][n4 + 0] = to_tf32(v.x - hx);
            Bs_hi[k][n4 + 1] = hy; Bs_lo[k][n4 + 1] = to_tf32(v.y - hy);
            Bs_hi[k][n4 + 2] = hz; Bs_lo[k][n4 + 2] = to_tf32(v.z - hz);
            Bs_hi[k][n4 + 3] = hw; Bs_lo[k][n4 + 3] = to_tf32(v.w - hw);
        }
        __syncthreads();

        #pragma unroll
        for (int k8 = 0; k8 < 16; k8 += 8) {
            const int kk = k8 + (lane & 3);
            uint32_t ah[2][4], al[2][4];
            #pragma unroll
            for (int mi = 0; mi < 2; mi++) {
                int r = wm + mi * 16 + (lane >> 2);
                ah[mi][0] = __float_as_uint(As_hi[r][kk]);
                ah[mi][1] = __float_as_uint(As_hi[r + 8][kk]);
                ah[mi][2] = __float_as_uint(As_hi[r][kk + 4]);
                ah[mi][3] = __float_as_uint(As_hi[r + 8][kk + 4]);
                al[mi][0] = __float_as_uint(As_lo[r][kk]);
                al[mi][1] = __float_as_uint(As_lo[r + 8][kk]);
                al[mi][2] = __float_as_uint(As_lo[r][kk + 4]);
                al[mi][3] = __float_as_uint(As_lo[r + 8][kk + 4]);
            }
            #pragma unroll
            for (int ni = 0; ni < 4; ni++) {
                int c = wn + ni * 8 + (lane >> 2);
                uint32_t bh0 = __float_as_uint(Bs_hi[kk][c]);
                uint32_t bh1 = __float_as_uint(Bs_hi[kk + 4][c]);
                uint32_t bl0 = __float_as_uint(Bs_lo[kk][c]);
                uint32_t bl1 = __float_as_uint(Bs_lo[kk + 4][c]);
                #pragma unroll
                for (int mi = 0; mi < 2; mi++) {
                    MMA_TF32(acc[mi][ni], ah[mi], bh0, bh1);
                    MMA_TF32(acc[mi][ni], al[mi], bh0, bh1);
                    MMA_TF32(acc[mi][ni], ah[mi], bl0, bl1);
                }
            }
        }
        __syncthreads();
    }

    #pragma unroll
    for (int mi = 0; mi < 2; mi++) {
        #pragma unroll
        for (int ni = 0; ni < 4; ni++) {
            int rbase = row0 + wm + mi * 16 + (lane >> 2);
            int cbase = col0 + wn + ni * 8 + (lane & 3) * 2;
            #pragma unroll
            for (int rr = 0; rr < 2; rr++) {
                int grow = rbase + rr * 8;
                if (grow >= NN) continue;
                #pragma unroll
                for (int cc = 0; cc < 2; cc++) {
                    int gc = cbase + cc;
                    float v = acc[mi][ni][rr * 2 + cc] + bias[gc];
                    if (gc >= 256) v = silu_f(v);
                    C[(size_t)grow * 384 + gc] = v;
                }
            }
        }
    }
}

// ---------------- GEMM2 + residual + LayerNorm fused --------------------------------
// hout = LN( h + [T | Hacc] @ Wk3 + bk3 , gamma, beta )
// BM=128, BN=128 (full width), BK=16, 256 threads, warp grid 4x2, warp tile 32x64.
__global__ __launch_bounds__(256)
void gemm2ln_kernel(const float* __restrict__ A0,   // T region: g_Z+256, stride 384
                    const float* __restrict__ A1,   // Hacc, stride 128
                    const float* __restrict__ W,    // 256x128
                    const float* __restrict__ bias,
                    const float* __restrict__ resid, // g_h
                    const float* __restrict__ gamma,
                    const float* __restrict__ beta,
                    float* __restrict__ C) {
    __shared__ float As_hi[128][20];
    __shared__ float As_lo[128][20];
    __shared__ float Bs_hi[16][136];
    __shared__ float Bs_lo[16][136];
    __shared__ float redS[2][128];
    __shared__ float redQ[2][128];

    const int tid  = threadIdx.x;
    const int lane = tid & 31;
    const int warp = tid >> 5;
    const int wm = (warp >> 1) * 32;
    const int wn = (warp & 1) * 64;
    const int row0 = blockIdx.x * 128;

    float acc[2][8][4];
    #pragma unroll
    for (int mi = 0; mi < 2; mi++)
        #pragma unroll
        for (int ni = 0; ni < 8; ni++)
            #pragma unroll
            for (int j = 0; j < 4; j++) acc[mi][ni][j] = 0.f;

    for (int kt = 0; kt < 256; kt += 16) {
        #pragma unroll
        for (int it = 0; it < 2; it++) {
            int idx = tid + it * 256;
            int m = idx >> 2;
            int k4 = (idx & 3) * 4;
            int grow = row0 + m;
            float4 v = make_float4(0.f, 0.f, 0.f, 0.f);
            if (grow < NN) {
                int gk = kt + k4;
                if (gk < 128) v = *(const float4*)(A0 + (size_t)grow * 384 + gk);
                else          v = *(const float4*)(A1 + (size_t)grow * 128 + (gk - 128));
            }
            float hx = to_tf32(v.x), hy = to_tf32(v.y), hz = to_tf32(v.z), hw = to_tf32(v.w);
            As_hi[m][k4 + 0] = hx; As_lo[m][k4 + 0] = to_tf32(v.x - hx);
            As_hi[m][k4 + 1] = hy; As_lo[m][k4 + 1] = to_tf32(v.y - hy);
            As_hi[m][k4 + 2] = hz; As_lo[m][k4 + 2] = to_tf32(v.z - hz);
            As_hi[m][k4 + 3] = hw; As_lo[m][k4 + 3] = to_tf32(v.w - hw);
        }
        #pragma unroll
        for (int it = 0; it < 2; it++) {
            int idx = tid + it * 256;
            int k = idx >> 5;
            int n4 = (idx & 31) * 4;
            float4 v = *(const float4*)(W + (size_t)(kt + k) * 128 + n4);
            float hx = to_tf32(v.x), hy = to_tf32(v.y), hz = to_tf32(v.z), hw = to_tf32(v.w);
            Bs_hi[k][n4 + 0] = hx; Bs_lo[k][n4 + 0] = to_tf32(v.x - hx);
            Bs_hi[k][n4 + 1] = hy; Bs_lo[k][n4 + 1] = to_tf32(v.y - hy);
            Bs_hi[k][n4 + 2] = hz; Bs_lo[k][n4 + 2] = to_tf32(v.z - hz);
            Bs_hi[k][n4 + 3] = hw; Bs_lo[k][n4 + 3] = to_tf32(v.w - hw);
        }
        __syncthreads();

        #pragma unroll
        for (int k8 = 0; k8 < 16; k8 += 8) {
            const int kk = k8 + (lane & 3);
            uint32_t ah[2][4], al[2][4];
            #pragma unroll
            for (int mi = 0; mi < 2; mi++) {
                int r = wm + mi * 16 + (lane >> 2);
                ah[mi][0] = __float_as_uint(As_hi[r][kk]);
                ah[mi][1] = __float_as_uint(As_hi[r + 8][kk]);
                ah[mi][2] = __float_as_uint(As_hi[r][kk + 4]);
                ah[mi][3] = __float_as_uint(As_hi[r + 8][kk + 4]);
                al[mi][0] = __float_as_uint(As_lo[r][kk]);
                al[mi][1] = __float_as_uint(As_lo[r + 8][kk]);
                al[mi][2] = __float_as_uint(As_lo[r][kk + 4]);
                al[mi][3] = __float_as_uint(As_lo[r + 8][kk + 4]);
            }
            #pragma unroll
            for (int ni = 0; ni < 8; ni++) {
                int c = wn + ni * 8 + (lane >> 2);
                uint32_t bh0 = __float_as_uint(Bs_hi[kk][c]);
                uint32_t bh1 = __float_as_uint(Bs_hi[kk + 4][c]);
                uint32_t bl0 = __float_as_uint(Bs_lo[kk][c]);
                uint32_t bl1 = __float_as_uint(Bs_lo[kk + 4][c]);
                #pragma unroll
                for (int mi = 0; mi < 2; mi++) {
                    MMA_TF32(acc[mi][ni], ah[mi], bh0, bh1);
                    MMA_TF32(acc[mi][ni], al[mi], bh0, bh1);
                    MMA_TF32(acc[mi][ni], ah[mi], bl0, bl1);
                }
            }
        }
        __syncthreads();
    }

    // ---- epilogue: v = acc + bias + resid; LN per row across 128 cols ----
    #pragma unroll
    for (int mi = 0; mi < 2; mi++) {
        #pragma unroll
        for (int rr = 0; rr < 2; rr++) {
            int rl = wm + mi * 16 + (lane >> 2) + rr * 8;
            int grow = row0 + rl;
            float s = 0.f, sq = 0.f;
            #pragma unroll
            for (int ni = 0; ni < 8; ni++) {
                #pragma unroll
                for (int cc = 0; cc < 2; cc++) {
                    int gc = wn + ni * 8 + (lane & 3) * 2 + cc;
                    float v = acc[mi][ni][rr * 2 + cc] + bias[gc];
                    if (grow < NN) v += resid[(size_t)grow * DD + gc];
                    acc[mi][ni][rr * 2 + cc] = v;
                    s += v;
                    sq = fmaf(v, v, sq);
                }
            }
            s  += __shfl_xor_sync(0xffffffffu, s, 1);
            s  += __shfl_xor_sync(0xffffffffu, s, 2);
            sq += __shfl_xor_sync(0xffffffffu, sq, 1);
            sq += __shfl_xor_sync(0xffffffffu, sq, 2);
            if ((lane & 3) == 0) {
                redS[warp & 1][rl] = s;
                redQ[warp & 1][rl] = sq;
            }
        }
    }
    __syncthreads();

    #pragma unroll
    for (int mi = 0; mi < 2; mi++) {
        #pragma unroll
        for (int rr = 0; rr < 2; rr++) {
            int rl = wm + mi * 16 + (lane >> 2) + rr * 8;
            int grow = row0 + rl;
            if (grow >= NN) continue;
            float st = redS[0][rl] + redS[1][rl];
            float qt = redQ[0][rl] + redQ[1][rl];
            float mean = st * (1.f / 128.f);
            float var = qt * (1.f / 128.f) - mean * mean;
            float rs = rsqrtf(var + 1e-5f);
            #pragma unroll
            for (int ni = 0; ni < 8; ni++) {
                #pragma unroll
                for (int cc = 0; cc < 2; cc++) {
                    int gc = wn + ni * 8 + (lane & 3) * 2 + cc;
                    float v = acc[mi][ni][rr * 2 + cc];
                    C[(size_t)grow * DD + gc] = (v - mean) * rs * __ldg(gamma + gc) + __ldg(beta + gc);
                }
            }
        }
    }
}

// ---------------- pos tail copy ------------------------------------------------------
__global__ void copy_pos_kernel(const float* __restrict__ pos, float* __restrict__ out) {
    int i = blockIdx.x * blockDim.x + threadIdx.x;
    if (i < NN * 3) out[NN * DD + i] = pos[i];
}

// ==================================================================================
extern "C" void kernel_launch(void* const* d_in, const int* in_sizes, int n_in,
                              void* d_out, int out_size) {
    const float* x        = (const float*)d_in[0];
    const float* pos      = (const float*)d_in[1];
    const float* time_emb = (const float*)d_in[2];
    const float* tw1      = (const float*)d_in[3];
    const float* tb1      = (const float*)d_in[4];
    const float* tw2      = (const float*)d_in[5];
    const float* tb2      = (const float*)d_in[6];
    const float* nw1      = (const float*)d_in[7];
    const float* nb1      = (const float*)d_in[8];
    const float* nw2      = (const float*)d_in[9];
    const float* nb2      = (const float*)d_in[10];
    const float* ew1      = (const float*)d_in[11];
    const float* eb1      = (const float*)d_in[12];
    const float* ew2      = (const float*)d_in[13];
    const float* eb2      = (const float*)d_in[14];
    const float* lng      = (const float*)d_in[15];
    const float* lnb      = (const float*)d_in[16];
    const void*  ei       = d_in[17];
    const void*  batch    = d_in[18];
    float* out = (float*)d_out;

    float *pH, *pZ, *pHacc, *pWk1, *pbk1, *pWk3, *pbk3;
    cudaGetSymbolAddress((void**)&pH,    g_h);
    cudaGetSymbolAddress((void**)&pZ,    g_Z);
    cudaGetSymbolAddress((void**)&pHacc, g_Hacc);
    cudaGetSymbolAddress((void**)&pWk1,  g_Wk1);
    cudaGetSymbolAddress((void**)&pbk1,  g_bk1);
    cudaGetSymbolAddress((void**)&pWk3,  g_Wk3);
    cudaGetSymbolAddress((void**)&pbk3,  g_bk3);

    detect_idx_kernel<<<1, 1>>>((const unsigned*)ei);
    pack_w_kernel<<<(LL * DD * 384 + 255) / 256, 256>>>(ew1, eb1, ew2, eb2, nw1, nb1, nw2, nb2);
    time_mlp_kernel<<<BB, DD>>>(time_emb, tw1, tb1, tw2, tb2);
    init_h_kernel<<<(NN * DD + 255) / 256, 256>>>(x, batch);
    prep_edges_kernel<<<(EE + 255) / 256, 256>>>(ei, pos);
    scanA_kernel<<<NB, 256>>>();
    scanB_kernel<<<1, 32>>>();
    scanC_kernel<<<(NN + 255) / 256, 256>>>();
    scatter_kernel<<<(EE + 255) / 256, 256>>>(ei);

    const int rowTiles = (NN + 127) / 128;  // 391
    for (int l = 0; l < LL; l++) {
        // Z = [P | Q | silu(T)] = h @ [W1a | W1b | nw1] + [b1 | 0 | nb1]
        gemm1_kernel<<<dim3(6, rowTiles), 256>>>(
            pH, pWk1 + (size_t)l * DD * 384, pbk1 + l * 384, pZ);

        // Hacc[n] = invdeg * sum over in-edges of silu(P[n]+Q[src]+dist*w1c)
        agg_kernel<<<(NN * 32 + 255) / 256, 256>>>(ew1 + (size_t)l * 257 * 128 + 256 * 128);

        // h = LN(h + [silu(T)|Hacc] @ [nw2;ew2] + (nb2+eb2))
        float* dst = (l == LL - 1) ? out : pH;
        gemm2ln_kernel<<<rowTiles, 256>>>(
            pZ + 256, pHacc,
            pWk3 + (size_t)l * 256 * DD, pbk3 + l * DD,
            pH, lng + l * DD, lnb + l * DD, dst);
    }

    copy_pos_kernel<<<(NN * 3 + 255) / 256, 256>>>(pos, out);
}

// round 4
// speedup vs baseline: 1.2435x; 1.0752x over previous
#include <cuda_runtime.h>
#include <cuda_fp16.h>
#include <math.h>
#include <stdint.h>

#define NN 50000
#define EE 800000
#define DD 128
#define BB 32
#define LL 3
#define NB ((NN + 255) / 256)

// ---------------- scratch (static device globals; no allocation) ----------------
__device__ float g_h[NN * DD];        // node state
__device__ float g_Z[NN * 384];       // [P | Q | T] per node
__device__ float g_Hacc[NN * DD];     // aggregated messages (pre-scaled by invdeg)
__device__ float g_tp[BB * DD];       // time projection
__device__ float g_dist[EE];          // per-edge distance (original edge order)
__device__ float g_invdeg[NN];
__device__ int   g_cnt[NN];           // in-degree
__device__ int   g_off[NN];           // CSR offsets
__device__ int   g_cursor[NN];        // scatter cursors
__device__ int   g_bsum[NB + 1];      // scan partials
__device__ int   g_er[EE];            // CSR: source node per slot
__device__ float g_edist[EE];         // CSR: distance per slot
__device__ float g_Wk1[LL * DD * 384];  // packed [W1a | W1b | nw1]
__device__ float g_bk1[LL * 384];
__device__ float g_Wk3[LL * 256 * DD];  // packed [nw2 ; ew2]
__device__ float g_bk3[LL * DD];        // nb2 + eb2
__device__ int   g_is64;

__device__ __forceinline__ float silu_f(float x) { return x / (1.f + __expf(-x)); }

__device__ __forceinline__ long long idx_at(const void* p, long long i) {
    if (g_is64) return ((const long long*)p)[i];
    return (long long)((const int*)p)[i];
}

// ---------------- dtype detection for edge_index / batch -------------------------
__global__ void detect_idx_kernel(const unsigned* w) {
    int is64 = 1;
    for (int i = 1; i < 256; i += 2)
        if (w[i] != 0u) { is64 = 0; break; }
    g_is64 = is64;
}

// ---------------- weight packing -------------------------------------------------
__global__ void pack_w_kernel(const float* __restrict__ ew1, const float* __restrict__ eb1,
                              const float* __restrict__ ew2, const float* __restrict__ eb2,
                              const float* __restrict__ nw1, const float* __restrict__ nb1,
                              const float* __restrict__ nw2, const float* __restrict__ nb2) {
    int idx = blockIdx.x * blockDim.x + threadIdx.x;
    if (idx < LL * DD * 384) {
        int l = idx / (DD * 384);
        int rem = idx % (DD * 384);
        int k = rem / 384;
        int j = rem % 384;
        float v;
        if (j < 128)       v = ew1[l * 257 * 128 + k * 128 + j];
        else if (j < 256)  v = ew1[l * 257 * 128 + (128 + k) * 128 + (j - 128)];
        else               v = nw1[l * 128 * 128 + k * 128 + (j - 256)];
        g_Wk1[idx] = v;
    }
    if (idx < LL * 256 * DD) {
        int l = idx / (256 * DD);
        int rem = idx % (256 * DD);
        int k = rem / DD;
        int j = rem % DD;
        float v = (k < 128) ? nw2[l * 128 * 128 + k * 128 + j]
                            : ew2[l * 128 * 128 + (k - 128) * 128 + j];
        g_Wk3[idx] = v;
    }
    if (idx < LL * 384) {
        int l = idx / 384;
        int j = idx % 384;
        float v;
        if (j < 128)      v = eb1[l * 128 + j];
        else if (j < 256) v = 0.f;
        else              v = nb1[l * 128 + (j - 256)];
        g_bk1[idx] = v;
    }
    if (idx < LL * DD) {
        g_bk3[idx] = nb2[idx] + eb2[idx];
    }
}

// ---------------- time MLP --------------------------------------------------------
__global__ void time_mlp_kernel(const float* __restrict__ te,
                                const float* __restrict__ tw1, const float* __restrict__ tb1,
                                const float* __restrict__ tw2, const float* __restrict__ tb2) {
    __shared__ float row[DD];
    __shared__ float hid[DD];
    int b = blockIdx.x;
    int j = threadIdx.x;
    row[j] = te[b * DD + j];
    __syncthreads();
    float s = tb1[j];
    #pragma unroll 8
    for (int k = 0; k < DD; k++) s = fmaf(row[k], tw1[k * DD + j], s);
    hid[j] = silu_f(s);
    __syncthreads();
    float s2 = tb2[j];
    #pragma unroll 8
    for (int k = 0; k < DD; k++) s2 = fmaf(hid[k], tw2[k * DD + j], s2);
    g_tp[b * DD + j] = s2;
}

// ---------------- h = x + tp[batch]; also zero g_cnt -------------------------------
__global__ void init_h_kernel(const float* __restrict__ x, const void* __restrict__ batch) {
    int idx = blockIdx.x * blockDim.x + threadIdx.x;
    if (idx < NN) g_cnt[idx] = 0;
    if (idx >= NN * DD) return;
    int n = idx >> 7;
    int d = idx & 127;
    long long bi = idx_at(batch, n);
    g_h[idx] = x[idx] + g_tp[(int)bi * DD + d];
}

// ---------------- edge prep: dist + int degree histogram ---------------------------
__global__ void prep_edges_kernel(const void* __restrict__ ei, const float* __restrict__ pos) {
    int e = blockIdx.x * blockDim.x + threadIdx.x;
    if (e >= EE) return;
    int r = (int)idx_at(ei, e);
    int c = (int)idx_at(ei, (long long)EE + e);
    float dx = pos[r * 3 + 0] - pos[c * 3 + 0];
    float dy = pos[r * 3 + 1] - pos[c * 3 + 1];
    float dz = pos[r * 3 + 2] - pos[c * 3 + 2];
    g_dist[e] = sqrtf(dx * dx + dy * dy + dz * dz);
    atomicAdd(&g_cnt[c], 1);
}

// ---------------- CSR scan ----------------------------------------------------------
__global__ void scanA_kernel() {
    __shared__ int sm[256];
    int i = blockIdx.x * 256 + threadIdx.x;
    int v = (i < NN) ? g_cnt[i] : 0;
    sm[threadIdx.x] = v;
    __syncthreads();
    #pragma unroll
    for (int o = 1; o < 256; o <<= 1) {
        int u = 0;
        if ((int)threadIdx.x >= o) u = sm[threadIdx.x - o];
        __syncthreads();
        sm[threadIdx.x] += u;
        __syncthreads();
    }
    if (i < NN) g_off[i] = sm[threadIdx.x] - v;
    if (threadIdx.x == 255) g_bsum[blockIdx.x] = sm[255];
}

__global__ void scanB_kernel() {
    if (threadIdx.x == 0) {
        int run = 0;
        for (int j = 0; j < NB; j++) {
            int t = g_bsum[j];
            g_bsum[j] = run;
            run += t;
        }
    }
}

__global__ void scanC_kernel() {
    int i = blockIdx.x * blockDim.x + threadIdx.x;
    if (i >= NN) return;
    int o = g_off[i] + g_bsum[i >> 8];
    g_off[i] = o;
    g_cursor[i] = o;
    g_invdeg[i] = 1.f / (float)max(g_cnt[i], 1);
}

// ---------------- scatter edges into CSR order -------------------------------------
__global__ void scatter_kernel(const void* __restrict__ ei) {
    int e = blockIdx.x * blockDim.x + threadIdx.x;
    if (e >= EE) return;
    int r = (int)idx_at(ei, e);
    int c = (int)idx_at(ei, (long long)EE + e);
    int p = atomicAdd(&g_cursor[c], 1);
    g_er[p] = r;
    g_edist[p] = g_dist[e];
}

// ---------------- aggregation: warp per node, no atomics ---------------------------
__global__ void agg_kernel(const float* __restrict__ w1c) {
    int t = blockIdx.x * blockDim.x + threadIdx.x;
    int n = t >> 5;
    int lane = t & 31;
    if (n >= NN) return;
    int start = g_off[n];
    int cnt = g_cnt[n];
    const float4 wc = *(const float4*)(w1c + lane * 4);
    const float4 p  = *(const float4*)(g_Z + (size_t)n * 384 + lane * 4);
    float4 acc = make_float4(0.f, 0.f, 0.f, 0.f);
    int i = 0;
    for (; i + 2 <= cnt; i += 2) {
        int r0 = g_er[start + i];
        int r1 = g_er[start + i + 1];
        float d0 = g_edist[start + i];
        float d1 = g_edist[start + i + 1];
        const float4 q0 = *(const float4*)(g_Z + (size_t)r0 * 384 + 128 + lane * 4);
        const float4 q1 = *(const float4*)(g_Z + (size_t)r1 * 384 + 128 + lane * 4);
        acc.x += silu_f(p.x + q0.x + d0 * wc.x) + silu_f(p.x + q1.x + d1 * wc.x);
        acc.y += silu_f(p.y + q0.y + d0 * wc.y) + silu_f(p.y + q1.y + d1 * wc.y);
        acc.z += silu_f(p.z + q0.z + d0 * wc.z) + silu_f(p.z + q1.z + d1 * wc.z);
        acc.w += silu_f(p.w + q0.w + d0 * wc.w) + silu_f(p.w + q1.w + d1 * wc.w);
    }
    if (i < cnt) {
        int r = g_er[start + i];
        float d = g_edist[start + i];
        const float4 q = *(const float4*)(g_Z + (size_t)r * 384 + 128 + lane * 4);
        acc.x += silu_f(p.x + q.x + d * wc.x);
        acc.y += silu_f(p.y + q.y + d * wc.y);
        acc.z += silu_f(p.z + q.z + d * wc.z);
        acc.w += silu_f(p.w + q.w + d * wc.w);
    }
    float s = g_invdeg[n];
    acc.x *= s; acc.y *= s; acc.z *= s; acc.w *= s;
    *(float4*)(g_Hacc + (size_t)n * DD + lane * 4) = acc;
}

// ---------------- fp16 split helpers + mma -------------------------------------------
#define MMA_F16(c, a, b0, b1)                                                     \
    asm volatile("mma.sync.aligned.m16n8k16.row.col.f32.f16.f16.f32 "             \
                 "{%0,%1,%2,%3}, {%4,%5,%6,%7}, {%8,%9}, {%0,%1,%2,%3};"          \
                 : "+f"(c[0]), "+f"(c[1]), "+f"(c[2]), "+f"(c[3])                 \
                 : "r"(a[0]), "r"(a[1]), "r"(a[2]), "r"(a[3]), "r"(b0), "r"(b1))

__device__ __forceinline__ void split_h(float v, __half& hi, __half& lo) {
    hi = __float2half_rn(v);
    lo = __float2half_rn(v - __half2float(hi));
}

#define APAD 24   // halves per A smem row (stride 12 words -> conflict-free frags)
#define BPAD 24   // halves per B smem row (k-packed)

// ---------------- GEMM1: Z = h @ Wk1 + bk1, silu on cols >= 256 --------------------
// BM=128, BN=64, BK=16, 256 threads, warp grid 4x2, warp tile 32x32.
__global__ __launch_bounds__(256)
void gemm1_kernel(const float* __restrict__ A,
                  const float* __restrict__ W, const float* __restrict__ bias,
                  float* __restrict__ C) {
    __shared__ __half As_hi[128][APAD];
    __shared__ __half As_lo[128][APAD];
    __shared__ __half Bs_hi[64][BPAD];   // [n][k]
    __shared__ __half Bs_lo[64][BPAD];

    const int tid  = threadIdx.x;
    const int lane = tid & 31;
    const int warp = tid >> 5;
    const int g4 = lane >> 2;      // 0..7
    const int t4 = lane & 3;       // 0..3
    const int wm = (warp >> 1) * 32;
    const int wn = (warp & 1) * 32;
    const int row0 = blockIdx.y * 128;
    const int col0 = blockIdx.x * 64;
    const int ncols = 384;

    float acc[2][4][4];
    #pragma unroll
    for (int mi = 0; mi < 2; mi++)
        #pragma unroll
        for (int ni = 0; ni < 4; ni++)
            #pragma unroll
            for (int j = 0; j < 4; j++) acc[mi][ni][j] = 0.f;

    for (int kt = 0; kt < 128; kt += 16) {
        // A tile: 128 rows x 16 k
        #pragma unroll
        for (int it = 0; it < 2; it++) {
            int idx = tid + it * 256;
            int m = idx >> 2;
            int k4 = (idx & 3) * 4;
            int grow = row0 + m;
            float4 v = make_float4(0.f, 0.f, 0.f, 0.f);
            if (grow < NN) v = *(const float4*)(A + (size_t)grow * DD + kt + k4);
            __half hx, lx, hy, ly, hz, lz, hw, lw;
            split_h(v.x, hx, lx); split_h(v.y, hy, ly);
            split_h(v.z, hz, lz); split_h(v.w, hw, lw);
            *(__half2*)&As_hi[m][k4]     = __halves2half2(hx, hy);
            *(__half2*)&As_hi[m][k4 + 2] = __halves2half2(hz, hw);
            *(__half2*)&As_lo[m][k4]     = __halves2half2(lx, ly);
            *(__half2*)&As_lo[m][k4 + 2] = __halves2half2(lz, lw);
        }
        // B tile: 16 k x 64 n, transposed into [n][k]
        {
            int k = tid >> 4;
            int n4 = (tid & 15) * 4;
            float4 v = *(const float4*)(W + (size_t)(kt + k) * ncols + col0 + n4);
            __half hi, lo;
            split_h(v.x, hi, lo); Bs_hi[n4 + 0][k] = hi; Bs_lo[n4 + 0][k] = lo;
            split_h(v.y, hi, lo); Bs_hi[n4 + 1][k] = hi; Bs_lo[n4 + 1][k] = lo;
            split_h(v.z, hi, lo); Bs_hi[n4 + 2][k] = hi; Bs_lo[n4 + 2][k] = lo;
            split_h(v.w, hi, lo); Bs_hi[n4 + 3][k] = hi; Bs_lo[n4 + 3][k] = lo;
        }
        __syncthreads();

        uint32_t ah[2][4], al[2][4];
        #pragma unroll
        for (int mi = 0; mi < 2; mi++) {
            int r = wm + mi * 16 + g4;
            ah[mi][0] = *(const uint32_t*)&As_hi[r][2 * t4];
            ah[mi][1] = *(const uint32_t*)&As_hi[r + 8][2 * t4];
            ah[mi][2] = *(const uint32_t*)&As_hi[r][2 * t4 + 8];
            ah[mi][3] = *(const uint32_t*)&As_hi[r + 8][2 * t4 + 8];
            al[mi][0] = *(const uint32_t*)&As_lo[r][2 * t4];
            al[mi][1] = *(const uint32_t*)&As_lo[r + 8][2 * t4];
            al[mi][2] = *(const uint32_t*)&As_lo[r][2 * t4 + 8];
            al[mi][3] = *(const uint32_t*)&As_lo[r + 8][2 * t4 + 8];
        }
        #pragma unroll
        for (int ni = 0; ni < 4; ni++) {
            int c = wn + ni * 8 + g4;
            uint32_t bh0 = *(const uint32_t*)&Bs_hi[c][2 * t4];
            uint32_t bh1 = *(const uint32_t*)&Bs_hi[c][2 * t4 + 8];
            uint32_t bl0 = *(const uint32_t*)&Bs_lo[c][2 * t4];
            uint32_t bl1 = *(const uint32_t*)&Bs_lo[c][2 * t4 + 8];
            #pragma unroll
            for (int mi = 0; mi < 2; mi++) {
                MMA_F16(acc[mi][ni], ah[mi], bh0, bh1);
                MMA_F16(acc[mi][ni], al[mi], bh0, bh1);
                MMA_F16(acc[mi][ni], ah[mi], bl0, bl1);
            }
        }
        __syncthreads();
    }

    #pragma unroll
    for (int mi = 0; mi < 2; mi++) {
        #pragma unroll
        for (int ni = 0; ni < 4; ni++) {
            int rbase = row0 + wm + mi * 16 + g4;
            int cbase = col0 + wn + ni * 8 + t4 * 2;
            #pragma unroll
            for (int rr = 0; rr < 2; rr++) {
                int grow = rbase + rr * 8;
                if (grow >= NN) continue;
                #pragma unroll
                for (int cc = 0; cc < 2; cc++) {
                    int gc = cbase + cc;
                    float v = acc[mi][ni][rr * 2 + cc] + bias[gc];
                    if (gc >= 256) v = silu_f(v);
                    C[(size_t)grow * 384 + gc] = v;
                }
            }
        }
    }
}

// ---------------- GEMM2 + residual + LayerNorm fused --------------------------------
// hout = LN( h + [T | Hacc] @ Wk3 + bk3 )
// BM=128, BN=128, BK=16, 256 threads, warp grid 4x2, warp tile 32x64.
__global__ __launch_bounds__(256)
void gemm2ln_kernel(const float* __restrict__ A0,   // T region: g_Z+256, stride 384
                    const float* __restrict__ A1,   // Hacc, stride 128
                    const float* __restrict__ W,    // 256x128
                    const float* __restrict__ bias,
                    const float* __restrict__ resid, // g_h
                    const float* __restrict__ gamma,
                    const float* __restrict__ beta,
                    float* __restrict__ C) {
    __shared__ __half As_hi[128][APAD];
    __shared__ __half As_lo[128][APAD];
    __shared__ __half Bs_hi[128][BPAD];
    __shared__ __half Bs_lo[128][BPAD];
    __shared__ float redS[2][128];
    __shared__ float redQ[2][128];

    const int tid  = threadIdx.x;
    const int lane = tid & 31;
    const int warp = tid >> 5;
    const int g4 = lane >> 2;
    const int t4 = lane & 3;
    const int wm = (warp >> 1) * 32;
    const int wn = (warp & 1) * 64;
    const int row0 = blockIdx.x * 128;

    float acc[2][8][4];
    #pragma unroll
    for (int mi = 0; mi < 2; mi++)
        #pragma unroll
        for (int ni = 0; ni < 8; ni++)
            #pragma unroll
            for (int j = 0; j < 4; j++) acc[mi][ni][j] = 0.f;

    for (int kt = 0; kt < 256; kt += 16) {
        #pragma unroll
        for (int it = 0; it < 2; it++) {
            int idx = tid + it * 256;
            int m = idx >> 2;
            int k4 = (idx & 3) * 4;
            int grow = row0 + m;
            float4 v = make_float4(0.f, 0.f, 0.f, 0.f);
            if (grow < NN) {
                int gk = kt + k4;
                if (gk < 128) v = *(const float4*)(A0 + (size_t)grow * 384 + gk);
                else          v = *(const float4*)(A1 + (size_t)grow * 128 + (gk - 128));
            }
            __half hx, lx, hy, ly, hz, lz, hw, lw;
            split_h(v.x, hx, lx); split_h(v.y, hy, ly);
            split_h(v.z, hz, lz); split_h(v.w, hw, lw);
            *(__half2*)&As_hi[m][k4]     = __halves2half2(hx, hy);
            *(__half2*)&As_hi[m][k4 + 2] = __halves2half2(hz, hw);
            *(__half2*)&As_lo[m][k4]     = __halves2half2(lx, ly);
            *(__half2*)&As_lo[m][k4 + 2] = __halves2half2(lz, lw);
        }
        // B tile: 16 k x 128 n transposed
        {
            int k = tid >> 4;
            int n8 = (tid & 15) * 8;
            #pragma unroll
            for (int jj = 0; jj < 8; jj += 4) {
                float4 v = *(const float4*)(W + (size_t)(kt + k) * 128 + n8 + jj);
                __half hi, lo;
                split_h(v.x, hi, lo); Bs_hi[n8 + jj + 0][k] = hi; Bs_lo[n8 + jj + 0][k] = lo;
                split_h(v.y, hi, lo); Bs_hi[n8 + jj + 1][k] = hi; Bs_lo[n8 + jj + 1][k] = lo;
                split_h(v.z, hi, lo); Bs_hi[n8 + jj + 2][k] = hi; Bs_lo[n8 + jj + 2][k] = lo;
                split_h(v.w, hi, lo); Bs_hi[n8 + jj + 3][k] = hi; Bs_lo[n8 + jj + 3][k] = lo;
            }
        }
        __syncthreads();

        uint32_t ah[2][4], al[2][4];
        #pragma unroll
        for (int mi = 0; mi < 2; mi++) {
            int r = wm + mi * 16 + g4;
            ah[mi][0] = *(const uint32_t*)&As_hi[r][2 * t4];
            ah[mi][1] = *(const uint32_t*)&As_hi[r + 8][2 * t4];
            ah[mi][2] = *(const uint32_t*)&As_hi[r][2 * t4 + 8];
            ah[mi][3] = *(const uint32_t*)&As_hi[r + 8][2 * t4 + 8];
            al[mi][0] = *(const uint32_t*)&As_lo[r][2 * t4];
            al[mi][1] = *(const uint32_t*)&As_lo[r + 8][2 * t4];
            al[mi][2] = *(const uint32_t*)&As_lo[r][2 * t4 + 8];
            al[mi][3] = *(const uint32_t*)&As_lo[r + 8][2 * t4 + 8];
        }
        #pragma unroll
        for (int ni = 0; ni < 8; ni++) {
            int c = wn + ni * 8 + g4;
            uint32_t bh0 = *(const uint32_t*)&Bs_hi[c][2 * t4];
            uint32_t bh1 = *(const uint32_t*)&Bs_hi[c][2 * t4 + 8];
            uint32_t bl0 = *(const uint32_t*)&Bs_lo[c][2 * t4];
            uint32_t bl1 = *(const uint32_t*)&Bs_lo[c][2 * t4 + 8];
            #pragma unroll
            for (int mi = 0; mi < 2; mi++) {
                MMA_F16(acc[mi][ni], ah[mi], bh0, bh1);
                MMA_F16(acc[mi][ni], al[mi], bh0, bh1);
                MMA_F16(acc[mi][ni], ah[mi], bl0, bl1);
            }
        }
        __syncthreads();
    }

    // ---- epilogue: v = acc + bias + resid; LN per row across 128 cols ----
    #pragma unroll
    for (int mi = 0; mi < 2; mi++) {
        #pragma unroll
        for (int rr = 0; rr < 2; rr++) {
            int rl = wm + mi * 16 + g4 + rr * 8;
            int grow = row0 + rl;
            float s = 0.f, sq = 0.f;
            #pragma unroll
            for (int ni = 0; ni < 8; ni++) {
                #pragma unroll
                for (int cc = 0; cc < 2; cc++) {
                    int gc = wn + ni * 8 + t4 * 2 + cc;
                    float v = acc[mi][ni][rr * 2 + cc] + bias[gc];
                    if (grow < NN) v += resid[(size_t)grow * DD + gc];
                    acc[mi][ni][rr * 2 + cc] = v;
                    s += v;
                    sq = fmaf(v, v, sq);
                }
            }
            s  += __shfl_xor_sync(0xffffffffu, s, 1);
            s  += __shfl_xor_sync(0xffffffffu, s, 2);
            sq += __shfl_xor_sync(0xffffffffu, sq, 1);
            sq += __shfl_xor_sync(0xffffffffu, sq, 2);
            if (t4 == 0) {
                redS[warp & 1][rl] = s;
                redQ[warp & 1][rl] = sq;
            }
        }
    }
    __syncthreads();

    #pragma unroll
    for (int mi = 0; mi < 2; mi++) {
        #pragma unroll
        for (int rr = 0; rr < 2; rr++) {
            int rl = wm + mi * 16 + g4 + rr * 8;
            int grow = row0 + rl;
            if (grow >= NN) continue;
            float st = redS[0][rl] + redS[1][rl];
            float qt = redQ[0][rl] + redQ[1][rl];
            float mean = st * (1.f / 128.f);
            float var = qt * (1.f / 128.f) - mean * mean;
            float rs = rsqrtf(var + 1e-5f);
            #pragma unroll
            for (int ni = 0; ni < 8; ni++) {
                #pragma unroll
                for (int cc = 0; cc < 2; cc++) {
                    int gc = wn + ni * 8 + t4 * 2 + cc;
                    float v = acc[mi][ni][rr * 2 + cc];
                    C[(size_t)grow * DD + gc] = (v - mean) * rs * __ldg(gamma + gc) + __ldg(beta + gc);
                }
            }
        }
    }
}

// ---------------- pos tail copy ------------------------------------------------------
__global__ void copy_pos_kernel(const float* __restrict__ pos, float* __restrict__ out) {
    int i = blockIdx.x * blockDim.x + threadIdx.x;
    if (i < NN * 3) out[NN * DD + i] = pos[i];
}

// ==================================================================================
extern "C" void kernel_launch(void* const* d_in, const int* in_sizes, int n_in,
                              void* d_out, int out_size) {
    const float* x        = (const float*)d_in[0];
    const float* pos      = (const float*)d_in[1];
    const float* time_emb = (const float*)d_in[2];
    const float* tw1      = (const float*)d_in[3];
    const float* tb1      = (const float*)d_in[4];
    const float* tw2      = (const float*)d_in[5];
    const float* tb2      = (const float*)d_in[6];
    const float* nw1      = (const float*)d_in[7];
    const float* nb1      = (const float*)d_in[8];
    const float* nw2      = (const float*)d_in[9];
    const float* nb2      = (const float*)d_in[10];
    const float* ew1      = (const float*)d_in[11];
    const float* eb1      = (const float*)d_in[12];
    const float* ew2      = (const float*)d_in[13];
    const float* eb2      = (const float*)d_in[14];
    const float* lng      = (const float*)d_in[15];
    const float* lnb      = (const float*)d_in[16];
    const void*  ei       = d_in[17];
    const void*  batch    = d_in[18];
    float* out = (float*)d_out;

    float *pH, *pZ, *pHacc, *pWk1, *pbk1, *pWk3, *pbk3;
    cudaGetSymbolAddress((void**)&pH,    g_h);
    cudaGetSymbolAddress((void**)&pZ,    g_Z);
    cudaGetSymbolAddress((void**)&pHacc, g_Hacc);
    cudaGetSymbolAddress((void**)&pWk1,  g_Wk1);
    cudaGetSymbolAddress((void**)&pbk1,  g_bk1);
    cudaGetSymbolAddress((void**)&pWk3,  g_Wk3);
    cudaGetSymbolAddress((void**)&pbk3,  g_bk3);

    detect_idx_kernel<<<1, 1>>>((const unsigned*)ei);
    pack_w_kernel<<<(LL * DD * 384 + 255) / 256, 256>>>(ew1, eb1, ew2, eb2, nw1, nb1, nw2, nb2);
    time_mlp_kernel<<<BB, DD>>>(time_emb, tw1, tb1, tw2, tb2);
    init_h_kernel<<<(NN * DD + 255) / 256, 256>>>(x, batch);
    prep_edges_kernel<<<(EE + 255) / 256, 256>>>(ei, pos);
    scanA_kernel<<<NB, 256>>>();
    scanB_kernel<<<1, 32>>>();
    scanC_kernel<<<(NN + 255) / 256, 256>>>();
    scatter_kernel<<<(EE + 255) / 256, 256>>>(ei);

    const int rowTiles = (NN + 127) / 128;  // 391
    for (int l = 0; l < LL; l++) {
        gemm1_kernel<<<dim3(6, rowTiles), 256>>>(
            pH, pWk1 + (size_t)l * DD * 384, pbk1 + l * 384, pZ);

        agg_kernel<<<(NN * 32 + 255) / 256, 256>>>(ew1 + (size_t)l * 257 * 128 + 256 * 128);

        float* dst = (l == LL - 1) ? out : pH;
        gemm2ln_kernel<<<rowTiles, 256>>>(
            pZ + 256, pHacc,
            pWk3 + (size_t)l * 256 * DD, pbk3 + l * DD,
            pH, lng + l * DD, lnb + l * DD, dst);
    }

    copy_pos_kernel<<<(NN * 3 + 255) / 256, 256>>>(pos, out);
}